// round 1
// baseline (speedup 1.0000x reference)
#include <cuda_runtime.h>
#include <stdint.h>

// Problem constants (from reference setup_inputs):
//   x:   [B=32, P=8, N=32, H=56, W=56] float32  -> [B, T=256, HW=3136]
//   idx: [C=64, k=4] int32, values in [0, 256)
//   out: [B, C=64, HW=3136] float32, out = (sum of 4 gathered bits >= 2) ? 1 : 0
#define B_    32
#define T_    256
#define HW_   3136
#define C_    64
#define K_    4
#define TPB   256
#define NPOS  (B_ * HW_)          // 100352 = 392 * 256 exactly

// Per-launch derived routing data (recomputed every launch; no caching).
__device__ int      g_n_used;
__device__ int      g_used[T_];      // compact list of used input channels
__device__ unsigned g_cidx[C_];      // 4 packed uint8 compact indices per output channel

// ---------------------------------------------------------------------------
// Preprocessing: mark used channels, build compact remap, pack per-output idx.
// One block, negligible cost (~256 ints of work).
// ---------------------------------------------------------------------------
__global__ void rp_preproc_kernel(const int* __restrict__ idx) {
    __shared__ int flag[T_];
    __shared__ int remap[T_];
    int t = threadIdx.x;                 // 256 threads
    flag[t] = 0;
    __syncthreads();
    // idx has exactly C_*K_ = 256 entries
    flag[idx[t]] = 1;                    // benign write race (all write 1)
    __syncthreads();
    if (t == 0) {
        int n = 0;
        for (int i = 0; i < T_; i++) {
            remap[i] = n;
            if (flag[i]) { g_used[n] = i; n++; }
        }
        g_n_used = n;
    }
    __syncthreads();
    if (t < C_) {
        unsigned e = 0;
        #pragma unroll
        for (int j = 0; j < K_; j++)
            e |= (unsigned)remap[idx[t * K_ + j]] << (8 * j);
        g_cidx[t] = e;
    }
}

// ---------------------------------------------------------------------------
// Main kernel: 1 thread = 1 spatial position (b, hw).
// Phase 1: load only used channels (coalesced), pack bits into smem via ballot.
// Phase 2: 64 outputs, 4 warp-broadcast LDS + bit extract each, coalesced STG.
// ---------------------------------------------------------------------------
__global__ void __launch_bounds__(TPB)
rp_fusion_kernel(const float* __restrict__ x, float* __restrict__ out) {
    // s_bits layout: [compact_channel][warp] -> 32 position-bits per word
    __shared__ unsigned s_bits[T_ * 8];   // 8 KB (8 warps/block)
    __shared__ unsigned s_cidx[C_];
    __shared__ int      s_used[T_];

    const int tid  = threadIdx.x;
    const int warp = tid >> 5;
    const int lane = tid & 31;
    const int n_used = g_n_used;

    if (tid < C_)     s_cidx[tid] = g_cidx[tid];
    if (tid < n_used) s_used[tid] = g_used[tid];
    __syncthreads();

    const int p  = blockIdx.x * TPB + tid;   // grid sized exactly: p < NPOS
    const int b  = p / HW_;
    const int hw = p - b * HW_;
    const int xbase = b * (T_ * HW_) + hw;

    // ---- Phase 1: stage bits of used channels into shared memory ----
    int i = 0;
    for (; i + 8 <= n_used; i += 8) {
        float v0 = x[xbase + s_used[i + 0] * HW_];
        float v1 = x[xbase + s_used[i + 1] * HW_];
        float v2 = x[xbase + s_used[i + 2] * HW_];
        float v3 = x[xbase + s_used[i + 3] * HW_];
        float v4 = x[xbase + s_used[i + 4] * HW_];
        float v5 = x[xbase + s_used[i + 5] * HW_];
        float v6 = x[xbase + s_used[i + 6] * HW_];
        float v7 = x[xbase + s_used[i + 7] * HW_];
        unsigned m0 = __ballot_sync(0xffffffffu, v0 != 0.0f);
        unsigned m1 = __ballot_sync(0xffffffffu, v1 != 0.0f);
        unsigned m2 = __ballot_sync(0xffffffffu, v2 != 0.0f);
        unsigned m3 = __ballot_sync(0xffffffffu, v3 != 0.0f);
        unsigned m4 = __ballot_sync(0xffffffffu, v4 != 0.0f);
        unsigned m5 = __ballot_sync(0xffffffffu, v5 != 0.0f);
        unsigned m6 = __ballot_sync(0xffffffffu, v6 != 0.0f);
        unsigned m7 = __ballot_sync(0xffffffffu, v7 != 0.0f);
        if (lane == 0) {
            s_bits[(i + 0) * 8 + warp] = m0;
            s_bits[(i + 1) * 8 + warp] = m1;
            s_bits[(i + 2) * 8 + warp] = m2;
            s_bits[(i + 3) * 8 + warp] = m3;
            s_bits[(i + 4) * 8 + warp] = m4;
            s_bits[(i + 5) * 8 + warp] = m5;
            s_bits[(i + 6) * 8 + warp] = m6;
            s_bits[(i + 7) * 8 + warp] = m7;
        }
    }
    for (; i < n_used; i++) {
        float v = x[xbase + s_used[i] * HW_];
        unsigned m = __ballot_sync(0xffffffffu, v != 0.0f);
        if (lane == 0) s_bits[i * 8 + warp] = m;
    }
    __syncthreads();

    // ---- Phase 2: compute 64 output channels ----
    const int obase = b * (C_ * HW_) + hw;
    #pragma unroll
    for (int c = 0; c < C_; c++) {
        unsigned e = s_cidx[c];
        int s = (int)((s_bits[((e      ) & 255u) * 8 + warp] >> lane) & 1u)
              + (int)((s_bits[((e >>  8) & 255u) * 8 + warp] >> lane) & 1u)
              + (int)((s_bits[((e >> 16) & 255u) * 8 + warp] >> lane) & 1u)
              + (int)((s_bits[((e >> 24)       ) * 8 + warp] >> lane) & 1u);
        out[obase + c * HW_] = (s >= 2) ? 1.0f : 0.0f;
    }
}

extern "C" void kernel_launch(void* const* d_in, const int* in_sizes, int n_in,
                              void* d_out, int out_size) {
    const float* x   = (const float*)d_in[0];
    const int*   idx = (const int*)  d_in[1];
    float*       out = (float*)d_out;
    (void)in_sizes; (void)n_in; (void)out_size;

    rp_preproc_kernel<<<1, TPB>>>(idx);
    rp_fusion_kernel<<<NPOS / TPB, TPB>>>(x, out);
}

// round 2
// speedup vs baseline: 1.0593x; 1.0593x over previous
#include <cuda_runtime.h>
#include <stdint.h>

// x:   [B=32, T=256, HW=3136] fp32 (0/1 values)
// idx: [C=64, k=4] int32 in [0,256)
// out: [B, C=64, HW] fp32,  out = (sum of 4 gathered bits >= 2) ? 1 : 0
#define B_    32
#define T_    256
#define HW_   3136
#define C_    64
#define NGRP  25              // ceil(3136 / 128) groups of 128 positions
#define WPROW (B_ * NGRP)     // 800 warp-tasks per channel (or per output channel)

// Per-launch routing state (recomputed every launch)
__device__ int      g_n_used;
__device__ int      g_used[T_];         // original channel ids that appear in idx
__device__ unsigned g_cidx[C_];         // 4 packed uint8 original-channel ids per output

// Bit-plane scratch: packed[b][ch][100] uint32 (25 groups x 4 words). 3.27 MB.
__device__ unsigned g_packed[B_ * T_ * (NGRP * 4)];

// ---------------------------------------------------------------------------
// Preprocess: build used-channel list (order irrelevant) + packed idx bytes.
// ---------------------------------------------------------------------------
__global__ void rp_preproc(const int* __restrict__ idx) {
    __shared__ int flag[T_];
    __shared__ int cnt;
    int t = threadIdx.x;                  // 256 threads
    flag[t] = 0;
    if (t == 0) cnt = 0;
    __syncthreads();
    flag[idx[t]] = 1;                     // 256 entries, benign race
    __syncthreads();
    if (flag[t]) { int p = atomicAdd(&cnt, 1); g_used[p] = t; }
    if (t < C_) {
        const int* r = idx + t * 4;
        g_cidx[t] = (unsigned)r[0] | ((unsigned)r[1] << 8)
                  | ((unsigned)r[2] << 16) | ((unsigned)r[3] << 24);
    }
    __syncthreads();
    if (t == 0) g_n_used = cnt;
}

// ---------------------------------------------------------------------------
// Pack: warp per (used-channel, b, group). float4 loads -> 4 ballots -> uint4.
// Bit order within a group: word j, bit l  <->  position g*128 + 4*l + j.
// ---------------------------------------------------------------------------
__global__ void __launch_bounds__(256)
rp_pack(const float* __restrict__ x) {
    int wg   = blockIdx.x * 8 + (threadIdx.x >> 5);
    int lane = threadIdx.x & 31;
    int ci   = wg / WPROW;
    if (ci >= g_n_used) return;           // uniform per warp
    int rem = wg - ci * WPROW;
    int b   = rem / NGRP;
    int g   = rem - b * NGRP;
    int ch  = g_used[ci];

    int pos = g * 128 + lane * 4;
    float4 v = make_float4(0.f, 0.f, 0.f, 0.f);
    if (pos < HW_)
        v = *(const float4*)(x + ((size_t)(b * T_ + ch) * HW_ + pos));

    unsigned m0 = __ballot_sync(0xffffffffu, v.x != 0.f);
    unsigned m1 = __ballot_sync(0xffffffffu, v.y != 0.f);
    unsigned m2 = __ballot_sync(0xffffffffu, v.z != 0.f);
    unsigned m3 = __ballot_sync(0xffffffffu, v.w != 0.f);

    if (lane == 0)
        *(uint4*)(&g_packed[(size_t)(b * T_ + ch) * (NGRP * 4) + g * 4]) =
            make_uint4(m0, m1, m2, m3);
}

// 2-of-4 per-bit majority
__device__ __forceinline__ unsigned maj2of4(unsigned a, unsigned b,
                                            unsigned c, unsigned d) {
    return (a & b) | (c & d) | ((a | b) & (c | d));
}

// ---------------------------------------------------------------------------
// Output: warp per (c, b, group). 4 uniform uint4 loads (L2-resident scratch),
// bitwise majority, coalesced float4 store.
// ---------------------------------------------------------------------------
__global__ void __launch_bounds__(256)
rp_out(float* __restrict__ out) {
    int wg   = blockIdx.x * 8 + (threadIdx.x >> 5);
    int lane = threadIdx.x & 31;
    int c    = wg / WPROW;                // [0, 64)
    int rem  = wg - c * WPROW;
    int b    = rem / NGRP;
    int g    = rem - b * NGRP;

    unsigned e = g_cidx[c];
    const uint4* base = (const uint4*)g_packed;   // uint4 index = (b*T+ch)*25 + g
    uint4 w0 = base[(size_t)(b * T_ + (e         & 255u)) * NGRP + g];
    uint4 w1 = base[(size_t)(b * T_ + ((e >>  8) & 255u)) * NGRP + g];
    uint4 w2 = base[(size_t)(b * T_ + ((e >> 16) & 255u)) * NGRP + g];
    uint4 w3 = base[(size_t)(b * T_ + ((e >> 24)        )) * NGRP + g];

    unsigned o0 = maj2of4(w0.x, w1.x, w2.x, w3.x);
    unsigned o1 = maj2of4(w0.y, w1.y, w2.y, w3.y);
    unsigned o2 = maj2of4(w0.z, w1.z, w2.z, w3.z);
    unsigned o3 = maj2of4(w0.w, w1.w, w2.w, w3.w);

    int pos = g * 128 + lane * 4;
    if (pos < HW_) {
        float4 r;
        r.x = (float)((o0 >> lane) & 1u);
        r.y = (float)((o1 >> lane) & 1u);
        r.z = (float)((o2 >> lane) & 1u);
        r.w = (float)((o3 >> lane) & 1u);
        *(float4*)(out + ((size_t)(b * C_ + c) * HW_ + pos)) = r;
    }
}

extern "C" void kernel_launch(void* const* d_in, const int* in_sizes, int n_in,
                              void* d_out, int out_size) {
    const float* x   = (const float*)d_in[0];
    const int*   idx = (const int*)  d_in[1];
    float*       out = (float*)d_out;
    (void)in_sizes; (void)n_in; (void)out_size;

    rp_preproc<<<1, 256>>>(idx);
    // pack: worst-case 256 channels x 800 warp-tasks, 8 warps/block
    rp_pack<<<(T_ * WPROW) / 8, 256>>>(x);
    // out: 64 channels x 800 warp-tasks
    rp_out<<<(C_ * WPROW) / 8, 256>>>(out);
}

// round 3
// speedup vs baseline: 1.7005x; 1.6053x over previous
#include <cuda_runtime.h>
#include <stdint.h>

// x:   [B=32, T=256, HW=3136] fp32 (0/1 values)
// idx: [C=64, k=4] int32 in [0,256)
// out: [B, C=64, HW] fp32 = (sum of 4 gathered bit-planes >= 2)
#define B_    32
#define T_    256
#define HW_   3136
#define C_    64
#define NGRP  25              // ceil(3136/128): groups of 128 positions
#define NIDX  (C_ * 4)        // 256 routing entries

// Bit-plane scratch: [b][ch][25 groups][4 words] uint32. 3.27 MB (L2-resident).
__device__ unsigned g_packed[B_ * T_ * (NGRP * 4)];

// ---------------------------------------------------------------------------
// Pack: warp per (ch, b) row. Block rebuilds the used-channel flags from idx
// (redundantly, deterministic, cheap). Unused channels exit immediately.
// Inner loop unrolled x5: 5 front-batched float4 loads (MLP=5) -> 20 ballots
// -> 5 consecutive uint4 stores (80B contiguous from lane 0).
// Bit convention: group g, word j, bit l  <->  position g*128 + 4*l + j.
// ---------------------------------------------------------------------------
__global__ void __launch_bounds__(256)
rp_pack(const float* __restrict__ x, const int* __restrict__ idx) {
    __shared__ unsigned char s_flag[T_];
    const int tid  = threadIdx.x;
    const int warp = tid >> 5;
    const int lane = tid & 31;

    s_flag[tid] = 0;
    __syncthreads();
    s_flag[__ldg(idx + tid)] = 1;      // 256 entries, benign race
    __syncthreads();

    const int wg = blockIdx.x * 8 + warp;   // grid covers 256*32 = 8192 warps
    const int ch = wg >> 5;                 // [0,256)
    const int b  = wg & 31;                 // [0,32)
    if (!s_flag[ch]) return;                // warp-uniform exit

    const float*    xrow = x + ((size_t)(b * T_ + ch) * HW_);
    unsigned* prow = &g_packed[(size_t)(b * T_ + ch) * (NGRP * 4)];

    #pragma unroll
    for (int g0 = 0; g0 < NGRP; g0 += 5) {
        float4 v[5];
        #pragma unroll
        for (int j = 0; j < 5; j++) {
            int pos = (g0 + j) * 128 + lane * 4;
            v[j] = (pos < HW_) ? *(const float4*)(xrow + pos)
                               : make_float4(0.f, 0.f, 0.f, 0.f);
        }
        #pragma unroll
        for (int j = 0; j < 5; j++) {
            unsigned m0 = __ballot_sync(0xffffffffu, v[j].x != 0.f);
            unsigned m1 = __ballot_sync(0xffffffffu, v[j].y != 0.f);
            unsigned m2 = __ballot_sync(0xffffffffu, v[j].z != 0.f);
            unsigned m3 = __ballot_sync(0xffffffffu, v[j].w != 0.f);
            if (lane == 0)
                *(uint4*)(prow + (g0 + j) * 4) = make_uint4(m0, m1, m2, m3);
        }
    }
}

// 2-of-4 per-bit majority: 1 iff at least 2 of {a,b,c,d} set.
__device__ __forceinline__ unsigned maj2of4(unsigned a, unsigned b,
                                            unsigned c, unsigned d) {
    return (a & b) | (c & d) | ((a | b) & (c | d));
}

// ---------------------------------------------------------------------------
// Out: warp per (c, b, g). idx read directly (L1/L2 broadcast), 4 uniform
// uint4 loads from L2-resident scratch, bitwise majority, coalesced STG.128.
// ---------------------------------------------------------------------------
__global__ void __launch_bounds__(256)
rp_out(const int* __restrict__ idx, float* __restrict__ out) {
    const int wg   = blockIdx.x * 8 + (threadIdx.x >> 5);  // 64*32*25 = 51200
    const int lane = threadIdx.x & 31;
    const int c    = wg / (B_ * NGRP);
    const int rem  = wg - c * (B_ * NGRP);
    const int b    = rem / NGRP;
    const int g    = rem - b * NGRP;

    const int e0 = __ldg(idx + c * 4 + 0);
    const int e1 = __ldg(idx + c * 4 + 1);
    const int e2 = __ldg(idx + c * 4 + 2);
    const int e3 = __ldg(idx + c * 4 + 3);

    const uint4* base = (const uint4*)g_packed;   // uint4 index = (b*T+ch)*25+g
    uint4 w0 = base[(size_t)(b * T_ + e0) * NGRP + g];
    uint4 w1 = base[(size_t)(b * T_ + e1) * NGRP + g];
    uint4 w2 = base[(size_t)(b * T_ + e2) * NGRP + g];
    uint4 w3 = base[(size_t)(b * T_ + e3) * NGRP + g];

    unsigned o0 = maj2of4(w0.x, w1.x, w2.x, w3.x);
    unsigned o1 = maj2of4(w0.y, w1.y, w2.y, w3.y);
    unsigned o2 = maj2of4(w0.z, w1.z, w2.z, w3.z);
    unsigned o3 = maj2of4(w0.w, w1.w, w2.w, w3.w);

    const int pos = g * 128 + lane * 4;
    if (pos < HW_) {
        float4 r;
        r.x = (float)((o0 >> lane) & 1u);
        r.y = (float)((o1 >> lane) & 1u);
        r.z = (float)((o2 >> lane) & 1u);
        r.w = (float)((o3 >> lane) & 1u);
        *(float4*)(out + ((size_t)(b * C_ + c) * HW_ + pos)) = r;
    }
}

extern "C" void kernel_launch(void* const* d_in, const int* in_sizes, int n_in,
                              void* d_out, int out_size) {
    const float* x   = (const float*)d_in[0];
    const int*   idx = (const int*)  d_in[1];
    float*       out = (float*)d_out;
    (void)in_sizes; (void)n_in; (void)out_size;

    rp_pack<<<(T_ * B_) / 8, 256>>>(x, idx);                 // 1024 blocks
    rp_out<<<(C_ * B_ * NGRP) / 8, 256>>>(idx, out);         // 6400 blocks
}

// round 4
// speedup vs baseline: 2.6329x; 1.5483x over previous
#include <cuda_runtime.h>
#include <stdint.h>

// x:   [B=32, T=256, HW=3136] fp32 (exact 0.0/1.0 values)
// idx: [C=64, k=4] int32 in [0,256)
// out: [B, C=64, HW] fp32 = (x[e0]+x[e1]+x[e2]+x[e3] >= 2) ? 1 : 0
#define B_    32
#define T_    256
#define HW_   3136
#define C_    64
#define NGRP  25               // ceil(3136/128) position groups of 128

// One fused kernel. Block = 256 threads owns (b, g): 128 positions x 64 output
// channels. Gather repeats (256 uses of ~162 unique rows) are L1/L2 hits
// because exactly one block touches each (b,g) slice. DRAM = 65MB in + 25.7MB out.
__global__ void __launch_bounds__(256)
rp_fused(const float* __restrict__ x, const int* __restrict__ idx,
         float* __restrict__ out) {
    __shared__ int s_idx[C_ * 4];

    const int tid  = threadIdx.x;
    const int warp = tid >> 5;
    const int lane = tid & 31;

    s_idx[tid] = __ldg(idx + tid);          // 256 routing entries
    __syncthreads();

    const int blk = blockIdx.x;             // 800 = 32 * 25
    const int b   = blk / NGRP;
    const int g   = blk - b * NGRP;
    const int pos = g * 128 + lane * 4;
    const bool ok = (pos < HW_);            // tail group g=24 has 64 valid pos

    const float* xb = x   + ((size_t)b * T_) * HW_ + pos;
    float*       ob = out + ((size_t)b * C_) * HW_ + pos;

    // Each warp computes 8 contiguous output channels; 2 channels per inner
    // step -> 8 independent LDG.128 in flight per thread.
    #pragma unroll
    for (int j0 = 0; j0 < 8; j0 += 2) {
        float4 v[2][4];
        int    cch[2];
        #pragma unroll
        for (int u = 0; u < 2; u++) {
            const int c = warp * 8 + j0 + u;
            cch[u] = c;
            const int e0 = s_idx[c * 4 + 0];
            const int e1 = s_idx[c * 4 + 1];
            const int e2 = s_idx[c * 4 + 2];
            const int e3 = s_idx[c * 4 + 3];
            if (ok) {
                v[u][0] = *(const float4*)(xb + (size_t)e0 * HW_);
                v[u][1] = *(const float4*)(xb + (size_t)e1 * HW_);
                v[u][2] = *(const float4*)(xb + (size_t)e2 * HW_);
                v[u][3] = *(const float4*)(xb + (size_t)e3 * HW_);
            }
        }
        #pragma unroll
        for (int u = 0; u < 2; u++) {
            if (ok) {
                float4 r;
                r.x = ((v[u][0].x + v[u][1].x) + (v[u][2].x + v[u][3].x) >= 2.0f) ? 1.0f : 0.0f;
                r.y = ((v[u][0].y + v[u][1].y) + (v[u][2].y + v[u][3].y) >= 2.0f) ? 1.0f : 0.0f;
                r.z = ((v[u][0].z + v[u][1].z) + (v[u][2].z + v[u][3].z) >= 2.0f) ? 1.0f : 0.0f;
                r.w = ((v[u][0].w + v[u][1].w) + (v[u][2].w + v[u][3].w) >= 2.0f) ? 1.0f : 0.0f;
                *(float4*)(ob + (size_t)cch[u] * HW_) = r;
            }
        }
    }
}

extern "C" void kernel_launch(void* const* d_in, const int* in_sizes, int n_in,
                              void* d_out, int out_size) {
    const float* x   = (const float*)d_in[0];
    const int*   idx = (const int*)  d_in[1];
    float*       out = (float*)d_out;
    (void)in_sizes; (void)n_in; (void)out_size;

    rp_fused<<<B_ * NGRP, 256>>>(x, idx, out);   // 800 blocks
}